// round 2
// baseline (speedup 1.0000x reference)
#include <cuda_runtime.h>
#include <math.h>

#define BB   4
#define TT   16
#define NN   2048
#define DD   64
#define EPSF 1e-4f
#define IEPS 1e4f
#define BTN  (BB*TT*NN)   // 131072

// scratch (static __device__ — no allocations)
__device__ float g_cX[BB*NN];
__device__ float g_cY[BB*NN];
__device__ float g_sqx[BB*NN];
__device__ float g_sqy[BB*NN];

__device__ __forceinline__ void fma2(unsigned long long &d,
                                     unsigned long long a,
                                     unsigned long long b) {
    asm("fma.rn.f32x2 %0, %1, %2, %0;" : "+l"(d) : "l"(a), "l"(b));
}

__global__ void init_kernel(float* __restrict__ out) {
    int id = blockIdx.x * blockDim.x + threadIdx.x;   // 0..8191
    if (id < 4) out[id * TT] = 0.f;                   // losses[:,0]
    int b = id >> 11, i = id & 2047;
    out[64 + (b * TT) * NN + i] = 0.f;                // f[:,0,:]
    out[64 + BTN + (b * TT) * NN + i] = 0.f;          // g[:,0,:]
}

__global__ void prep_kernel(int step,
                            const float* __restrict__ x, const float* __restrict__ y,
                            const float* __restrict__ loga, const float* __restrict__ logb,
                            const float* __restrict__ out) {
    int id = blockIdx.x * 256 + threadIdx.x;          // 0..32767
    int kind = id >> 13;
    int r = id & 8191;
    int b = r >> 11, i = r & 2047;
    const float* v;
    if (kind == 0)      v = y + ((size_t)(b * TT + step - 1) * NN + i) * DD;
    else if (kind == 1) v = x + ((size_t)(b * TT + step - 1) * NN + i) * DD;
    else if (kind == 2) v = x + ((size_t)(b * TT + step) * NN + i) * DD;
    else                v = y + ((size_t)(b * TT + step) * NN + i) * DD;
    float s = 0.f;
    const float4* v4 = (const float4*)v;
#pragma unroll
    for (int k = 0; k < 16; k++) {
        float4 q = v4[k];
        s += q.x * q.x + q.y * q.y + q.z * q.z + q.w * q.w;
    }
    int bi = b * NN + i;
    if (kind == 0) {
        float gprev = out[64 + BTN + (b * TT + step - 1) * NN + i];
        float lb    = logb[(b * TT + step - 1) * NN + i];
        g_cY[bi] = gprev + EPSF * lb - s;
    } else if (kind == 1) {
        float fprev = out[64 + (b * TT + step - 1) * NN + i];
        float la    = loga[(b * TT + step - 1) * NN + i];
        g_cX[bi] = fprev + EPSF * la - s;
    } else if (kind == 2) {
        g_sqx[bi] = s;
    } else {
        g_sqy[bi] = s;
    }
}

// Fused GEMM (2*X*Y^T) + streaming logsumexp.
// grid = 128 blocks: dir(2) x b(4) x rowblock(16). 256 threads.
// Block tile: 128 rows x 64 cols x d=64, packed f32x2 along d.
__global__ __launch_bounds__(256, 1)
void main_kernel(int step,
                 const float* __restrict__ x, const float* __restrict__ y,
                 float* __restrict__ out) {
    __shared__ unsigned long long As2[32][128];   // [k-pair][row]  32 KB
    __shared__ unsigned long long Bs2[32][64];    // [k-pair][col]  16 KB

    const int tid = threadIdx.x;
    const int bid = blockIdx.x;
    const int dir = bid >> 6;
    const int b   = (bid >> 4) & 3;
    const int rb  = bid & 15;
    const int r0  = rb * 128;

    const float* A    = (dir == 0 ? x : y) + (size_t)((b * TT + step) * NN) * DD;
    const float* Bk   = (dir == 0 ? y : x) + (size_t)((b * TT + step - 1) * NN) * DD;
    const float* cvec = (dir == 0 ? g_cY : g_cX) + b * NN;
    const float* sqv  = (dir == 0 ? g_sqx : g_sqy) + b * NN;

    // Load A tile (128 rows x 32 pairs), transposed-packed into SMEM
    {
        const unsigned long long* Ag =
            (const unsigned long long*)(A + (size_t)r0 * DD);
#pragma unroll
        for (int j = 0; j < 16; j++) {
            int idx = tid + 256 * j;           // = row*32 + pair
            As2[idx & 31][idx >> 5] = Ag[idx];
        }
    }

    const int cg  = tid & 15;        // col group (4 cols)
    const int rg  = tid >> 4;        // row group (8 rows)
    const int rth = rg * 8;
    const int cth = cg * 4;

    float rmax[8], rsum[8];
#pragma unroll
    for (int i = 0; i < 8; i++) { rmax[i] = -INFINITY; rsum[i] = 0.f; }

    // prefetch first B tile into registers
    unsigned long long breg[8];
    {
        const unsigned long long* Bg = (const unsigned long long*)Bk;
#pragma unroll
        for (int j = 0; j < 8; j++) breg[j] = Bg[tid + 256 * j];
    }

    for (int mt = 0; mt < NN / 64; mt++) {
        __syncthreads();
#pragma unroll
        for (int j = 0; j < 8; j++) {
            int idx = tid + 256 * j;           // = col*32 + pair
            Bs2[idx & 31][idx >> 5] = breg[j];
        }
        __syncthreads();
        if (mt < NN / 64 - 1) {
            const unsigned long long* Bg =
                (const unsigned long long*)Bk + (size_t)(mt + 1) * 64 * 32;
#pragma unroll
            for (int j = 0; j < 8; j++) breg[j] = Bg[tid + 256 * j];
        }

        float cc0 = __ldg(&cvec[mt * 64 + cth + 0]);
        float cc1 = __ldg(&cvec[mt * 64 + cth + 1]);
        float cc2 = __ldg(&cvec[mt * 64 + cth + 2]);
        float cc3 = __ldg(&cvec[mt * 64 + cth + 3]);

        unsigned long long acc[32];
#pragma unroll
        for (int i = 0; i < 32; i++) acc[i] = 0ull;

#pragma unroll 8
        for (int k2 = 0; k2 < 32; k2++) {
            unsigned long long a[8], bv[4];
            ulonglong2 t;
            t = *(const ulonglong2*)&As2[k2][rth + 0]; a[0] = t.x; a[1] = t.y;
            t = *(const ulonglong2*)&As2[k2][rth + 2]; a[2] = t.x; a[3] = t.y;
            t = *(const ulonglong2*)&As2[k2][rth + 4]; a[4] = t.x; a[5] = t.y;
            t = *(const ulonglong2*)&As2[k2][rth + 6]; a[6] = t.x; a[7] = t.y;
            t = *(const ulonglong2*)&Bs2[k2][cth + 0]; bv[0] = t.x; bv[1] = t.y;
            t = *(const ulonglong2*)&Bs2[k2][cth + 2]; bv[2] = t.x; bv[3] = t.y;
#pragma unroll
            for (int r = 0; r < 8; r++)
#pragma unroll
                for (int c = 0; c < 4; c++)
                    fma2(acc[r * 4 + c], a[r], bv[c]);
        }

        // epilogue: p = 2*dot + c, streaming (max, sum*exp) per row
#pragma unroll
        for (int r = 0; r < 8; r++) {
            float p[4];
#pragma unroll
            for (int c = 0; c < 4; c++) {
                unsigned long long v = acc[r * 4 + c];
                float lo  = __uint_as_float((unsigned int)v);
                float hi  = __uint_as_float((unsigned int)(v >> 32));
                float dot = lo + hi;
                float cc  = (c == 0) ? cc0 : (c == 1) ? cc1 : (c == 2) ? cc2 : cc3;
                p[c] = 2.f * dot + cc;
            }
            float tm = fmaxf(fmaxf(p[0], p[1]), fmaxf(p[2], p[3]));
            float nm = fmaxf(tm, rmax[r]);
            rsum[r] *= __expf((rmax[r] - nm) * IEPS);
            rmax[r] = nm;
            rsum[r] += __expf((p[0] - nm) * IEPS) + __expf((p[1] - nm) * IEPS)
                     + __expf((p[2] - nm) * IEPS) + __expf((p[3] - nm) * IEPS);
        }
    }

    // cross-thread combine: 16 partial (max,sum) per row
    __syncthreads();
    float* comb = (float*)&As2[0][0];   // 128 rows * 16 * 2 floats = 16 KB
#pragma unroll
    for (int i = 0; i < 8; i++) {
        comb[(rth + i) * 32 + cg * 2 + 0] = rmax[i];
        comb[(rth + i) * 32 + cg * 2 + 1] = rsum[i];
    }
    __syncthreads();
    if (tid < 128) {
        float M = -INFINITY;
#pragma unroll
        for (int j = 0; j < 16; j++) M = fmaxf(M, comb[tid * 32 + 2 * j]);
        float S = 0.f;
#pragma unroll
        for (int j = 0; j < 16; j++)
            S += comb[tid * 32 + 2 * j + 1] * __expf((comb[tid * 32 + 2 * j] - M) * IEPS);
        int row = r0 + tid;
        float val = sqv[row] - M - EPSF * logf(S);
        out[64 + (dir ? BTN : 0) + (size_t)(b * TT + step) * NN + row] = val;
    }
}

// Deterministic loss reduction: one block, double accumulation.
__global__ void loss_kernel(int step, const float* __restrict__ loga,
                            float* __restrict__ out) {
    __shared__ double sm[256];
    int tid = threadIdx.x;
    double acc = 0.0;
    for (int idx = tid; idx < BB * NN; idx += 256) {
        int b = idx >> 11, i = idx & 2047;
        int o = (b * TT + step) * NN + i;
        float fa = out[64 + o];
        float ga = out[64 + BTN + o];
        float la = loga[o];
        acc += (double)expf(la) * ((double)fa + (double)ga);
    }
    sm[tid] = acc;
    __syncthreads();
    for (int s = 128; s > 0; s >>= 1) {
        if (tid < s) sm[tid] += sm[tid + s];
        __syncthreads();
    }
    if (tid == 0) {
        float L = (float)sm[0];
#pragma unroll
        for (int b = 0; b < BB; b++) out[b * TT + step] = L;
    }
}

extern "C" void kernel_launch(void* const* d_in, const int* in_sizes, int n_in,
                              void* d_out, int out_size) {
    const float* x    = (const float*)d_in[0];
    const float* y    = (const float*)d_in[1];
    const float* loga = (const float*)d_in[2];
    const float* logb = (const float*)d_in[3];
    float* out = (float*)d_out;

    init_kernel<<<32, 256>>>(out);
    for (int step = 1; step < TT; step++) {
        prep_kernel<<<128, 256>>>(step, x, y, loga, logb, out);
        main_kernel<<<128, 256>>>(step, x, y, out);
        loss_kernel<<<1, 256>>>(step, loga, out);
    }
}

// round 4
// speedup vs baseline: 1.3965x; 1.3965x over previous
#include <cuda_runtime.h>
#include <math.h>

#define BB   4
#define TT   16
#define NN   2048
#define DD   64
#define EPSF 1e-4f
#define IEPS 1e4f
#define BTN  (BB*TT*NN)   // 131072 = 2^17

typedef unsigned long long u64;

// scratch (static __device__ — no allocations)
__device__ float  g_sqx[BTN];
__device__ float  g_sqy[BTN];
__device__ double g_lossPart[128];

__device__ __forceinline__ void fma2(u64 &d, u64 a, u64 b) {
    asm("fma.rn.f32x2 %0, %1, %2, %0;" : "+l"(d) : "l"(a), "l"(b));
}

// Precompute ALL row squared-norms once (deterministic, graph-capturable).
__global__ void norms_kernel(const float* __restrict__ x, const float* __restrict__ y) {
    int id = blockIdx.x * 256 + threadIdx.x;      // 0 .. 2*BTN-1
    int kind = id >> 17;                           // BTN = 2^17
    int r = id & (BTN - 1);
    const float4* v = (const float4*)((kind ? y : x) + (size_t)r * DD);
    float s = 0.f;
#pragma unroll
    for (int k = 0; k < 16; k++) {
        float4 q = v[k];
        s += q.x * q.x + q.y * q.y + q.z * q.z + q.w * q.w;
    }
    (kind ? g_sqy : g_sqx)[r] = s;
}

__global__ void init_kernel(float* __restrict__ out) {
    int id = blockIdx.x * blockDim.x + threadIdx.x;   // 0..8191
    if (id < 4) out[id * TT] = 0.f;                   // losses[:,0]
    int b = id >> 11, i = id & 2047;
    out[64 + (b * TT) * NN + i] = 0.f;                // f[:,0,:]
    out[64 + BTN + (b * TT) * NN + i] = 0.f;          // g[:,0,:]
}

// Fused GEMM (2*X*Y^T + c) + streaming soft-min + per-block loss partial.
// grid = 128 blocks: dir(2) x b(4) x rowblock(16). 256 threads.
// Block tile 128 rows x 128 cols x d=64 (packed f32x2), thread tile 8x8.
// Dynamic SMEM: As2 [32][128] u64 (32KB) | Bs2 [32][128] u64 (32KB) | Cs [2048] f32 (8KB)
__global__ __launch_bounds__(256, 1)
void main_kernel(int step,
                 const float* __restrict__ x, const float* __restrict__ y,
                 const float* __restrict__ loga, const float* __restrict__ logb,
                 float* __restrict__ out) {
    extern __shared__ char smem[];
    u64*   As2 = (u64*)smem;
    u64*   Bs2 = (u64*)(smem + 32768);
    float* Cs  = (float*)(smem + 65536);

    const int tid = threadIdx.x;
    const int bid = blockIdx.x;
    const int dir = bid >> 6;
    const int b   = (bid >> 4) & 3;
    const int rb  = bid & 15;
    const int r0  = rb * 128;

    const size_t curBase  = (size_t)(b * TT + step) * NN;
    const size_t prevBase = (size_t)(b * TT + step - 1) * NN;

    const float* A       = (dir == 0 ? x : y) + curBase * DD;
    const float* Bk      = (dir == 0 ? y : x) + prevBase * DD;
    const float* prevPot = out + 64 + (dir == 0 ? BTN : 0);  // dir0: g_prev, dir1: f_prev
    const float* lvec    = (dir == 0 ? logb : loga);
    const float* sqPrev  = (dir == 0 ? g_sqy : g_sqx);
    const float* sqCur   = (dir == 0 ? g_sqx : g_sqy);

    // A tile (128 rows x 32 pairs) -> swizzled transposed SMEM
    {
        const u64* Ag = (const u64*)(A + (size_t)r0 * DD);
#pragma unroll
        for (int j = 0; j < 16; j++) {
            int idx = tid + 256 * j;               // row*32 + pair
            int pair = idx & 31, row = idx >> 5;
            As2[pair * 128 + (row ^ ((pair & 15) << 1))] = Ag[idx];
        }
    }
    // c vector for all 2048 cols: c = pot_prev + EPS*log(ab) - ||.||^2
#pragma unroll
    for (int j = 0; j < 8; j++) {
        int col = tid + 256 * j;
        Cs[col] = prevPot[prevBase + col] + EPSF * lvec[prevBase + col]
                - sqPrev[prevBase + col];
    }

    const int rg  = tid >> 4, cg = tid & 15;
    const int rth = rg * 8,  cg2 = cg * 2;

    float rmax[8], rsum[8];
#pragma unroll
    for (int i = 0; i < 8; i++) { rmax[i] = -INFINITY; rsum[i] = 0.f; }

    const u64* Bg = (const u64*)Bk;

    for (int mt = 0; mt < 16; mt++) {
        __syncthreads();
        {
            const u64* Bg2 = Bg + (size_t)mt * 4096;
#pragma unroll
            for (int j = 0; j < 16; j++) {
                int idx = tid + 256 * j;           // col*32 + pair
                int pair = idx & 31, col = idx >> 5;
                Bs2[pair * 128 + (col ^ ((pair & 15) << 1))] = Bg2[idx];
            }
        }
        __syncthreads();

        u64 acc[64];
#pragma unroll
        for (int i = 0; i < 64; i++) acc[i] = 0ull;

#pragma unroll 4
        for (int k2 = 0; k2 < 32; k2++) {
            const int swz = (k2 & 15) << 1;
            const int sl  = swz & 6;
            const int sh  = swz & 24;
            const u64* Ak = As2 + k2 * 128;
            const u64* Bq = Bs2 + k2 * 128;
            u64 a[8], bv[8];
            int abase = rth ^ sh;
#pragma unroll
            for (int j = 0; j < 4; j++) {
                ulonglong2 t = *(const ulonglong2*)&Ak[abase + ((2 * j) ^ sl)];
                a[2 * j] = t.x; a[2 * j + 1] = t.y;
            }
            int bbase = cg2 ^ swz;
#pragma unroll
            for (int h = 0; h < 4; h++) {
                ulonglong2 t = *(const ulonglong2*)&Bq[bbase + 32 * h];
                bv[2 * h] = t.x; bv[2 * h + 1] = t.y;
            }
#pragma unroll
            for (int r = 0; r < 8; r++)
#pragma unroll
                for (int c = 0; c < 8; c++)
                    fma2(acc[r * 8 + c], a[r], bv[c]);
        }

        // epilogue: p = 2*dot + c; streaming (max, sum) per row with
        // bit-exact underflow skip (exp((p-nm)*1e4) == 0 when p < nm - 0.0089)
        float cc[8];
#pragma unroll
        for (int c = 0; c < 8; c++)
            cc[c] = Cs[mt * 128 + cg2 + (c & 1) + 32 * (c >> 1)];
#pragma unroll
        for (int r = 0; r < 8; r++) {
            float p[8];
#pragma unroll
            for (int c = 0; c < 8; c++) {
                u64 v = acc[r * 8 + c];
                float lo = __uint_as_float((unsigned)v);
                float hi = __uint_as_float((unsigned)(v >> 32));
                p[c] = fmaf(2.f, lo + hi, cc[c]);
            }
            float tm = p[0];
#pragma unroll
            for (int c = 1; c < 8; c++) tm = fmaxf(tm, p[c]);
            if (tm > rmax[r] - 0.0090f) {
                float nm = fmaxf(tm, rmax[r]);
                float s = 0.f;
#pragma unroll
                for (int c = 0; c < 8; c++) s += __expf((p[c] - nm) * IEPS);
                rsum[r] = rsum[r] * __expf((rmax[r] - nm) * IEPS) + s;
                rmax[r] = nm;
            }
        }
    }

    // cross-thread combine: 16 partial (max,sum) per row
    __syncthreads();
    float* comb = (float*)As2;   // 128 rows * 32 floats = 16KB (reuse)
#pragma unroll
    for (int i = 0; i < 8; i++) {
        comb[(rth + i) * 32 + cg2]     = rmax[i];
        comb[(rth + i) * 32 + cg2 + 1] = rsum[i];
    }
    __syncthreads();

    double contrib = 0.0;
    if (tid < 128) {
        float M = -INFINITY;
#pragma unroll
        for (int j = 0; j < 16; j++) M = fmaxf(M, comb[tid * 32 + 2 * j]);
        float S = 0.f;
#pragma unroll
        for (int j = 0; j < 16; j++)
            S += comb[tid * 32 + 2 * j + 1] * __expf((comb[tid * 32 + 2 * j] - M) * IEPS);
        int row = r0 + tid;
        float val = sqCur[curBase + row] - M - EPSF * logf(S);
        out[64 + (dir ? BTN : 0) + curBase + row] = val;
        contrib = (double)__expf(loga[curBase + row]) * (double)val;
    }
    // deterministic per-block loss partial
    double* dsm = (double*)Bs2;  // 256 doubles (reuse)
    dsm[tid] = contrib;
    __syncthreads();
    for (int s = 128; s > 0; s >>= 1) {
        if (tid < s) dsm[tid] += dsm[tid + s];
        __syncthreads();
    }
    if (tid == 0) g_lossPart[bid] = dsm[0];
}

// Tiny deterministic finish: sum 128 block partials, broadcast to losses[:,step].
__global__ void loss_finish(int step, float* __restrict__ out) {
    __shared__ double sm[128];
    int tid = threadIdx.x;
    sm[tid] = g_lossPart[tid];
    __syncthreads();
    for (int s = 64; s > 0; s >>= 1) {
        if (tid < s) sm[tid] += sm[tid + s];
        __syncthreads();
    }
    if (tid < 4) out[tid * TT + step] = (float)sm[0];
}

extern "C" void kernel_launch(void* const* d_in, const int* in_sizes, int n_in,
                              void* d_out, int out_size) {
    const float* x    = (const float*)d_in[0];
    const float* y    = (const float*)d_in[1];
    const float* loga = (const float*)d_in[2];
    const float* logb = (const float*)d_in[3];
    float* out = (float*)d_out;

    const int smem_bytes = 73728;  // 32K + 32K + 8K
    cudaFuncSetAttribute(main_kernel, cudaFuncAttributeMaxDynamicSharedMemorySize,
                         smem_bytes);

    norms_kernel<<<1024, 256>>>(x, y);
    init_kernel<<<32, 256>>>(out);
    for (int step = 1; step < TT; step++) {
        main_kernel<<<128, 256, smem_bytes>>>(step, x, y, loga, logb, out);
        loss_finish<<<1, 128>>>(step, out);
    }
}

// round 6
// speedup vs baseline: 2.6281x; 1.8819x over previous
#include <cuda_runtime.h>
#include <cuda_bf16.h>
#include <math.h>
#include <stdint.h>

#define BB   4
#define TT   16
#define NN   2048
#define DD   64
#define EPSF 1e-4f
#define IEPS 1e4f
#define BTN  (BB*TT*NN)   // 131072 = 2^17

typedef unsigned long long u64;

// static device scratch (no allocations)
__device__ float  g_sqx[BTN];
__device__ float  g_sqy[BTN];
__device__ double g_lossPart[2][128];
// bf16 split storage: per row 128 bf16: [0:64]=hi, [64:128]=lo
__device__ __nv_bfloat16 g_xs[(size_t)BTN * 128];
__device__ __nv_bfloat16 g_ys[(size_t)BTN * 128];

__device__ __forceinline__ uint32_t smem_u32(const void* p) {
    uint32_t a;
    asm("{ .reg .u64 t; cvta.to.shared.u64 t, %1; cvt.u32.u64 %0, t; }"
        : "=r"(a) : "l"(p));
    return a;
}
__device__ __forceinline__ void ldsm4(uint32_t* r, uint32_t addr) {
    asm volatile("ldmatrix.sync.aligned.m8n8.x4.shared.b16 {%0,%1,%2,%3}, [%4];"
        : "=r"(r[0]), "=r"(r[1]), "=r"(r[2]), "=r"(r[3]) : "r"(addr));
}
__device__ __forceinline__ void mma16816(float* d, const uint32_t* a,
                                         const uint32_t* b) {
    asm volatile(
        "mma.sync.aligned.m16n8k16.row.col.f32.bf16.bf16.f32 "
        "{%0,%1,%2,%3}, {%4,%5,%6,%7}, {%8,%9}, {%0,%1,%2,%3};"
        : "+f"(d[0]), "+f"(d[1]), "+f"(d[2]), "+f"(d[3])
        : "r"(a[0]), "r"(a[1]), "r"(a[2]), "r"(a[3]), "r"(b[0]), "r"(b[1]));
}

// ---------------- small kernels ----------------
__global__ void split_kernel(const float* __restrict__ x, const float* __restrict__ y) {
    int id = blockIdx.x * 256 + threadIdx.x;       // 0 .. 2*BTN*16-1
    int kind = id >> 21;                            // BTN*16 = 2^21
    int r = id & ((1 << 21) - 1);
    int row = r >> 4, c4 = (r & 15) << 2;
    const float* src = (kind ? y : x) + (size_t)row * DD + c4;
    float4 v = *(const float4*)src;
    union { __nv_bfloat16 h[4]; u64 v; } H, L;
    H.h[0] = __float2bfloat16(v.x); L.h[0] = __float2bfloat16(v.x - __bfloat162float(H.h[0]));
    H.h[1] = __float2bfloat16(v.y); L.h[1] = __float2bfloat16(v.y - __bfloat162float(H.h[1]));
    H.h[2] = __float2bfloat16(v.z); L.h[2] = __float2bfloat16(v.z - __bfloat162float(H.h[2]));
    H.h[3] = __float2bfloat16(v.w); L.h[3] = __float2bfloat16(v.w - __bfloat162float(H.h[3]));
    __nv_bfloat16* dst = (kind ? g_ys : g_xs) + (size_t)row * 128 + c4;
    *(u64*)dst = H.v;
    *(u64*)(dst + 64) = L.v;
}

__global__ void norms_kernel(const float* __restrict__ x, const float* __restrict__ y) {
    int id = blockIdx.x * 256 + threadIdx.x;
    int kind = id >> 17;
    int r = id & (BTN - 1);
    const float4* v = (const float4*)((kind ? y : x) + (size_t)r * DD);
    float s = 0.f;
#pragma unroll
    for (int k = 0; k < 16; k++) {
        float4 q = v[k];
        s += q.x * q.x + q.y * q.y + q.z * q.z + q.w * q.w;
    }
    (kind ? g_sqy : g_sqx)[r] = s;
}

__global__ void init_kernel(float* __restrict__ out) {
    int id = blockIdx.x * blockDim.x + threadIdx.x;   // 0..8191
    if (id < 4) out[id * TT] = 0.f;
    int b = id >> 11, i = id & 2047;
    out[64 + (b * TT) * NN + i] = 0.f;
    out[64 + BTN + (b * TT) * NN + i] = 0.f;
}

// ---------------- main mma.sync kernel ----------------
// SMEM: A 0..32K | B0 32K..64K | B1 64K..96K | Cs 96K..104K |
//       comb 104K..108K | dsm 108K..110K
#define OFF_B0   32768
#define OFF_B1   65536
#define OFF_CS   98304
#define OFF_COMB 106496
#define OFF_DSM  110592
#define SMEM_TOT 112640

__global__ __launch_bounds__(256, 1)
void main_kernel(int step, const float* __restrict__ loga,
                 const float* __restrict__ logb, float* __restrict__ out) {
    extern __shared__ char smem[];
    const uint32_t sb = smem_u32(smem);
    float*  Cs   = (float*)(smem + OFF_CS);
    float*  comb = (float*)(smem + OFF_COMB);
    double* dsm  = (double*)(smem + OFF_DSM);

    const int tid = threadIdx.x;
    const int bid = blockIdx.x;
    const int dir = bid >> 6;
    const int b   = (bid >> 4) & 3;
    const int rb  = bid & 15;
    const int r0  = rb * 128;
    const int lane = tid & 31, wid = tid >> 5;
    const int warp_r = wid >> 2, warp_c = wid & 3;

    const size_t curBase  = (size_t)(b * TT + step) * NN;
    const size_t prevBase = curBase - NN;

    const __nv_bfloat16* Abase = (dir == 0 ? g_xs : g_ys) + (curBase + r0) * 128;
    const __nv_bfloat16* Bbase = (dir == 0 ? g_ys : g_xs) + prevBase * 128;
    const float* prevPot = out + 64 + (dir == 0 ? BTN : 0);
    const float* lvec    = (dir == 0 ? logb : loga);
    const float* sqPrev  = (dir == 0 ? g_sqy : g_sqx);
    const float* sqCur   = (dir == 0 ? g_sqx : g_sqy);

    // A tile (resident) + B tile 0 + c vector
#pragma unroll
    for (int j = 0; j < 8; j++) {
        int idx = tid + 256 * j;
        int row = idx >> 4, ch = idx & 15;
        uint4 v = ((const uint4*)(Abase + (size_t)row * 128))[ch];
        *(uint4*)(smem + row * 256 + ((ch ^ (row & 7)) << 4)) = v;
    }
#pragma unroll
    for (int j = 0; j < 8; j++) {
        int idx = tid + 256 * j;
        int row = idx >> 4, ch = idx & 15;
        uint4 v = ((const uint4*)(Bbase + (size_t)row * 128))[ch];
        *(uint4*)(smem + OFF_B0 + row * 256 + ((ch ^ (row & 7)) << 4)) = v;
    }
#pragma unroll
    for (int j = 0; j < 8; j++) {
        int col = tid + 256 * j;
        Cs[col] = prevPot[prevBase + col] + EPSF * lvec[prevBase + col]
                - sqPrev[prevBase + col];
    }
    __syncthreads();

    // per-lane ldmatrix bases
    const int a_row = lane & 15, a_chi = lane >> 4;
    const int aswz  = a_row & 7;
    uint32_t abase[4];
#pragma unroll
    for (int i = 0; i < 4; i++)
        abase[i] = sb + (uint32_t)((warp_r * 64 + i * 16 + a_row) * 256);
    const int b_row = (lane & 7) + ((lane >> 4) & 1) * 8;
    const int b_chi = (lane >> 3) & 1;
    const int bswz  = lane & 7;
    uint32_t bbase[2];
#pragma unroll
    for (int jp = 0; jp < 2; jp++)
        bbase[jp] = (uint32_t)((warp_c * 32 + jp * 16 + b_row) * 256);

    float acc[4][4][4];
#pragma unroll
    for (int i = 0; i < 4; i++)
#pragma unroll
        for (int j = 0; j < 4; j++)
#pragma unroll
            for (int q = 0; q < 4; q++) acc[i][j][q] = 0.f;

    float rmax[8], rsum[8];
#pragma unroll
    for (int i = 0; i < 8; i++) { rmax[i] = -INFINITY; rsum[i] = 0.f; }

    uint4 bpref[8];

    for (int t = 0; t < 16; t++) {
        // prefetch next B tile (overlaps compute)
        if (t + 1 < 16) {
            const __nv_bfloat16* Bt = Bbase + (size_t)(t + 1) * 128 * 128;
#pragma unroll
            for (int j = 0; j < 8; j++) {
                int idx = tid + 256 * j;
                int row = idx >> 4, ch = idx & 15;
                bpref[j] = ((const uint4*)(Bt + (size_t)row * 128))[ch];
            }
        }
        const uint32_t sBuf = sb + ((t & 1) ? OFF_B1 : OFF_B0);

        // 3 groups (hi*hi, lo*hi, hi*lo) x 4 k16-steps
#pragma unroll
        for (int g = 0; g < 3; g++) {
            const int cha = (g == 1) ? 8 : 0;
            const int chb = (g == 2) ? 8 : 0;
#pragma unroll
            for (int s = 0; s < 4; s++) {
                uint32_t afr[4][4], bfr[2][4];
#pragma unroll
                for (int i = 0; i < 4; i++)
                    ldsm4(afr[i], abase[i] + (((cha + 2 * s + a_chi) ^ aswz) << 4));
#pragma unroll
                for (int jp = 0; jp < 2; jp++)
                    ldsm4(bfr[jp], sBuf + bbase[jp]
                                 + (((chb + 2 * s + b_chi) ^ bswz) << 4));
#pragma unroll
                for (int i = 0; i < 4; i++)
#pragma unroll
                    for (int j = 0; j < 4; j++)
                        mma16816(acc[i][j], afr[i], &bfr[j >> 1][(j & 1) * 2]);
            }
        }

        // epilogue on register fragments
        {
            const float* Ct = Cs + t * 128 + warp_c * 32 + 2 * (lane & 3);
            float cc[8];
#pragma unroll
            for (int j = 0; j < 4; j++) { cc[2*j] = Ct[j*8]; cc[2*j+1] = Ct[j*8+1]; }
#pragma unroll
            for (int i = 0; i < 4; i++)
#pragma unroll
                for (int h = 0; h < 2; h++) {
                    float p[8];
#pragma unroll
                    for (int j = 0; j < 4; j++) {
                        p[2*j]   = fmaf(2.f, acc[i][j][2*h],     cc[2*j]);
                        p[2*j+1] = fmaf(2.f, acc[i][j][2*h + 1], cc[2*j+1]);
                    }
                    float tm = p[0];
#pragma unroll
                    for (int j = 1; j < 8; j++) tm = fmaxf(tm, p[j]);
                    const int r8 = i * 2 + h;
                    if (tm > rmax[r8] - 0.0090f) {  // else all exps underflow to 0
                        float nm = fmaxf(tm, rmax[r8]);
                        float s2 = 0.f;
#pragma unroll
                        for (int j = 0; j < 8; j++)
                            s2 += __expf((p[j] - nm) * IEPS);
                        rsum[r8] = rsum[r8] * __expf((rmax[r8] - nm) * IEPS) + s2;
                        rmax[r8] = nm;
                    }
                }
#pragma unroll
            for (int i = 0; i < 4; i++)
#pragma unroll
                for (int j = 0; j < 4; j++)
#pragma unroll
                    for (int q = 0; q < 4; q++) acc[i][j][q] = 0.f;
        }

        // store next B tile into the other buffer (safe: last read in tile t-1,
        // and all warps passed the end-of-iter t-1 barrier before reaching here)
        if (t + 1 < 16) {
            char* Bd = smem + (((t + 1) & 1) ? OFF_B1 : OFF_B0);
#pragma unroll
            for (int j = 0; j < 8; j++) {
                int idx = tid + 256 * j;
                int row = idx >> 4, ch = idx & 15;
                *(uint4*)(Bd + row * 256 + ((ch ^ (row & 7)) << 4)) = bpref[j];
            }
        }
        __syncthreads();
    }

    // in-warp combine over the 4 lanes sharing a row
#pragma unroll
    for (int r8 = 0; r8 < 8; r8++) {
        float m = rmax[r8], s = rsum[r8];
#pragma unroll
        for (int off = 1; off <= 2; off <<= 1) {
            float om = __shfl_xor_sync(0xffffffffu, m, off);
            float os = __shfl_xor_sync(0xffffffffu, s, off);
            float nm = fmaxf(m, om);
            s = s * __expf((m - nm) * IEPS) + os * __expf((om - nm) * IEPS);
            m = nm;
        }
        if ((lane & 3) == 0) {
            int rl = warp_r * 64 + (r8 >> 1) * 16 + (r8 & 1) * 8 + (lane >> 2);
            comb[(rl * 4 + warp_c) * 2]     = m;
            comb[(rl * 4 + warp_c) * 2 + 1] = s;
        }
    }
    __syncthreads();

    double contrib = 0.0;
    if (tid < 128) {
        float M = comb[tid * 8], S = comb[tid * 8 + 1];
#pragma unroll
        for (int w = 1; w < 4; w++) {
            float m = comb[(tid * 4 + w) * 2], s = comb[(tid * 4 + w) * 2 + 1];
            float nm = fmaxf(M, m);
            S = S * __expf((M - nm) * IEPS) + s * __expf((m - nm) * IEPS);
            M = nm;
        }
        int row = r0 + tid;
        float val = sqCur[curBase + row] - M - EPSF * logf(S);
        out[64 + (dir ? BTN : 0) + curBase + row] = val;
        contrib = (double)__expf(loga[curBase + row]) * (double)val;
    }
    dsm[tid] = contrib;
    __syncthreads();
    for (int s = 128; s > 0; s >>= 1) {
        if (tid < s) dsm[tid] += dsm[tid + s];
        __syncthreads();
    }
    if (tid == 0) g_lossPart[step & 1][bid] = dsm[0];

    // finish the PREVIOUS step's loss (written by the previous launch)
    if (bid == 0 && tid == 0 && step > 1) {
        double s = 0.0;
#pragma unroll 8
        for (int i = 0; i < 128; i++) s += g_lossPart[(step - 1) & 1][i];
        float L = (float)s;
#pragma unroll
        for (int bq = 0; bq < BB; bq++) out[bq * TT + step - 1] = L;
    }
}

// final step's loss
__global__ void loss_finish(float* __restrict__ out) {
    __shared__ double sm[128];
    int tid = threadIdx.x;
    sm[tid] = g_lossPart[(TT - 1) & 1][tid];
    __syncthreads();
    for (int s = 64; s > 0; s >>= 1) {
        if (tid < s) sm[tid] += sm[tid + s];
        __syncthreads();
    }
    if (tid < 4) out[tid * TT + (TT - 1)] = (float)sm[0];
}

extern "C" void kernel_launch(void* const* d_in, const int* in_sizes, int n_in,
                              void* d_out, int out_size) {
    const float* x    = (const float*)d_in[0];
    const float* y    = (const float*)d_in[1];
    const float* loga = (const float*)d_in[2];
    const float* logb = (const float*)d_in[3];
    float* out = (float*)d_out;

    cudaFuncSetAttribute(main_kernel, cudaFuncAttributeMaxDynamicSharedMemorySize,
                         SMEM_TOT);

    split_kernel<<<16384, 256>>>(x, y);
    norms_kernel<<<1024, 256>>>(x, y);
    init_kernel<<<32, 256>>>(out);
    for (int step = 1; step < TT; step++) {
        main_kernel<<<128, 256, SMEM_TOT>>>(step, loga, logb, out);
    }
    loss_finish<<<1, 128>>>(out);
}

// round 8
// speedup vs baseline: 3.4049x; 1.2956x over previous
#include <cuda_runtime.h>
#include <cuda_bf16.h>
#include <math.h>
#include <stdint.h>

#define BB   4
#define TT   16
#define NN   2048
#define DD   64
#define EPSF 1e-4f
#define IEPS 1e4f
#define BTN  (BB*TT*NN)   // 131072 = 2^17

typedef unsigned long long u64;

// static device scratch (no allocations)
__device__ float  g_sqx[BTN];
__device__ float  g_sqy[BTN];
__device__ double g_lossPart[2][256];
// bf16 split storage: per row 128 bf16: [0:64]=hi, [64:128]=lo
__device__ __nv_bfloat16 g_xs[(size_t)BTN * 128];
__device__ __nv_bfloat16 g_ys[(size_t)BTN * 128];

__device__ __forceinline__ uint32_t smem_u32(const void* p) {
    uint32_t a;
    asm("{ .reg .u64 t; cvta.to.shared.u64 t, %1; cvt.u32.u64 %0, t; }"
        : "=r"(a) : "l"(p));
    return a;
}
__device__ __forceinline__ void ldsm4(uint32_t* r, uint32_t addr) {
    asm volatile("ldmatrix.sync.aligned.m8n8.x4.shared.b16 {%0,%1,%2,%3}, [%4];"
        : "=r"(r[0]), "=r"(r[1]), "=r"(r[2]), "=r"(r[3]) : "r"(addr));
}
__device__ __forceinline__ void mma16816(float* d, const uint32_t* a,
                                         const uint32_t* b) {
    asm volatile(
        "mma.sync.aligned.m16n8k16.row.col.f32.bf16.bf16.f32 "
        "{%0,%1,%2,%3}, {%4,%5,%6,%7}, {%8,%9}, {%0,%1,%2,%3};"
        : "+f"(d[0]), "+f"(d[1]), "+f"(d[2]), "+f"(d[3])
        : "r"(a[0]), "r"(a[1]), "r"(a[2]), "r"(a[3]), "r"(b[0]), "r"(b[1]));
}
__device__ __forceinline__ void cpasync16(uint32_t sm, const void* g) {
    asm volatile("cp.async.cg.shared.global [%0], [%1], 16;"
                 :: "r"(sm), "l"(g));
}
#define CP_COMMIT() asm volatile("cp.async.commit_group;" ::: "memory")

// ---------------- small kernels ----------------
__global__ void split_kernel(const float* __restrict__ x, const float* __restrict__ y) {
    int id = blockIdx.x * 256 + threadIdx.x;       // 0 .. 2*BTN*16-1
    int kind = id >> 21;                            // BTN*16 = 2^21
    int r = id & ((1 << 21) - 1);
    int row = r >> 4, c4 = (r & 15) << 2;
    const float* src = (kind ? y : x) + (size_t)row * DD + c4;
    float4 v = *(const float4*)src;
    union { __nv_bfloat16 h[4]; u64 v; } H, L;
    H.h[0] = __float2bfloat16(v.x); L.h[0] = __float2bfloat16(v.x - __bfloat162float(H.h[0]));
    H.h[1] = __float2bfloat16(v.y); L.h[1] = __float2bfloat16(v.y - __bfloat162float(H.h[1]));
    H.h[2] = __float2bfloat16(v.z); L.h[2] = __float2bfloat16(v.z - __bfloat162float(H.h[2]));
    H.h[3] = __float2bfloat16(v.w); L.h[3] = __float2bfloat16(v.w - __bfloat162float(H.h[3]));
    __nv_bfloat16* dst = (kind ? g_ys : g_xs) + (size_t)row * 128 + c4;
    *(u64*)dst = H.v;
    *(u64*)(dst + 64) = L.v;
}

__global__ void norms_kernel(const float* __restrict__ x, const float* __restrict__ y) {
    int id = blockIdx.x * 256 + threadIdx.x;
    int kind = id >> 17;
    int r = id & (BTN - 1);
    const float4* v = (const float4*)((kind ? y : x) + (size_t)r * DD);
    float s = 0.f;
#pragma unroll
    for (int k = 0; k < 16; k++) {
        float4 q = v[k];
        s += q.x * q.x + q.y * q.y + q.z * q.z + q.w * q.w;
    }
    (kind ? g_sqy : g_sqx)[r] = s;
}

__global__ void init_kernel(float* __restrict__ out) {
    int id = blockIdx.x * blockDim.x + threadIdx.x;   // 0..8191
    if (id < 4) out[id * TT] = 0.f;
    int b = id >> 11, i = id & 2047;
    out[64 + (b * TT) * NN + i] = 0.f;
    out[64 + BTN + (b * TT) * NN + i] = 0.f;
}

// ---------------- main mma.sync kernel ----------------
// grid = 256: dir(2) x b(4) x rowblock(32). Block tile 64 rows x 2048 cols.
// 2 CTAs/SM co-resident. SMEM layout:
//   A 0..16K | B0 16K..48K | B1 48K..80K | Cs 80K..88K | comb 88K..90K | dsm 90K..92K
#define OFF_B    16384
#define OFF_CS   81920
#define OFF_COMB 90112
#define OFF_DSM  92160
#define SMEM_TOT 94208

__global__ __launch_bounds__(256, 2)
void main_kernel(int step, const float* __restrict__ loga,
                 const float* __restrict__ logb, float* __restrict__ out) {
    extern __shared__ char smem[];
    const uint32_t sb = smem_u32(smem);
    float*  Cs   = (float*)(smem + OFF_CS);
    float*  comb = (float*)(smem + OFF_COMB);
    double* dsm  = (double*)(smem + OFF_DSM);

    const int tid = threadIdx.x;
    const int bid = blockIdx.x;
    const int dir = bid >> 7;
    const int b   = (bid >> 5) & 3;
    const int rb  = bid & 31;
    const int r0  = rb * 64;
    const int lane = tid & 31, wid = tid >> 5;
    const int warp_r = wid >> 2, warp_c = wid & 3;

    const size_t curBase  = (size_t)(b * TT + step) * NN;
    const size_t prevBase = curBase - NN;

    const __nv_bfloat16* Abase = (dir == 0 ? g_xs : g_ys) + (curBase + r0) * 128;
    const __nv_bfloat16* Bbase = (dir == 0 ? g_ys : g_xs) + prevBase * 128;
    const float* prevPot = out + 64 + (dir == 0 ? BTN : 0);
    const float* lvec    = (dir == 0 ? logb : loga);
    const float* sqPrev  = (dir == 0 ? g_sqy : g_sqx);
    const float* sqCur   = (dir == 0 ? g_sqx : g_sqy);

    // per-thread load slot: idx = tid + 256*j -> row = idx>>4, ch = idx&15
    const int ld_row0 = tid >> 4, ld_ch = tid & 15;

    // A tile (64 rows x 16 chunks = 1024 chunks): 4 per thread, via cp.async
#pragma unroll
    for (int j = 0; j < 4; j++) {
        int row = ld_row0 + 16 * j;
        cpasync16(sb + (uint32_t)(row * 256 + ((ld_ch ^ (row & 7)) << 4)),
                  Abase + (size_t)row * 128 + ld_ch * 8);
    }
    // B tile 0 (128 rows x 16 chunks): 8 per thread
#pragma unroll
    for (int j = 0; j < 8; j++) {
        int row = ld_row0 + 16 * j;
        cpasync16(sb + OFF_B + (uint32_t)(row * 256 + ((ld_ch ^ (row & 7)) << 4)),
                  Bbase + (size_t)row * 128 + ld_ch * 8);
    }
    CP_COMMIT();
    // c vector: c = pot_prev + EPS*log(ab) - ||prev||^2
#pragma unroll
    for (int j = 0; j < 8; j++) {
        int col = tid + 256 * j;
        Cs[col] = prevPot[prevBase + col] + EPSF * lvec[prevBase + col]
                - sqPrev[prevBase + col];
    }

    // per-lane ldmatrix bases
    const int a_row = lane & 15, a_chi = lane >> 4;
    const int aswz  = a_row & 7;
    uint32_t abase[2];
#pragma unroll
    for (int i = 0; i < 2; i++)
        abase[i] = sb + (uint32_t)((warp_r * 32 + i * 16 + a_row) * 256);
    const int b_row = (lane & 7) + ((lane >> 4) & 1) * 8;
    const int b_chi = (lane >> 3) & 1;
    const int bswz  = lane & 7;
    uint32_t bbase[2];
#pragma unroll
    for (int jp = 0; jp < 2; jp++)
        bbase[jp] = (uint32_t)((warp_c * 32 + jp * 16 + b_row) * 256);

    float acc[2][4][4];
#pragma unroll
    for (int i = 0; i < 2; i++)
#pragma unroll
        for (int j = 0; j < 4; j++)
#pragma unroll
            for (int q = 0; q < 4; q++) acc[i][j][q] = 0.f;

    float rmax[4], rsum[4];
#pragma unroll
    for (int i = 0; i < 4; i++) { rmax[i] = -INFINITY; rsum[i] = 0.f; }

#pragma unroll 1
    for (int t = 0; t < 16; t++) {
        __syncthreads();   // all warps done computing t-1 -> buf[(t+1)&1] free
        if (t + 1 < 16) {
            const __nv_bfloat16* Bt = Bbase + (size_t)(t + 1) * 128 * 128;
            uint32_t Bd = sb + OFF_B + (uint32_t)(((t + 1) & 1) << 15);
#pragma unroll
            for (int j = 0; j < 8; j++) {
                int row = ld_row0 + 16 * j;
                cpasync16(Bd + (uint32_t)(row * 256 + ((ld_ch ^ (row & 7)) << 4)),
                          Bt + (size_t)row * 128 + ld_ch * 8);
            }
            CP_COMMIT();
            asm volatile("cp.async.wait_group 1;" ::: "memory");
        } else {
            asm volatile("cp.async.wait_group 0;" ::: "memory");
        }
        __syncthreads();   // tile t data visible to all

        const uint32_t sBuf = sb + OFF_B + (uint32_t)((t & 1) << 15);

        // 3 groups (hi*hi, lo*hi, hi*lo) x 4 k16-steps
#pragma unroll
        for (int g = 0; g < 3; g++) {
            const int cha = (g == 1) ? 8 : 0;
            const int chb = (g == 2) ? 8 : 0;
#pragma unroll
            for (int s = 0; s < 4; s++) {
                uint32_t afr[2][4], bfr[2][4];
#pragma unroll
                for (int i = 0; i < 2; i++)
                    ldsm4(afr[i], abase[i] + (((cha + 2 * s + a_chi) ^ aswz) << 4));
#pragma unroll
                for (int jp = 0; jp < 2; jp++)
                    ldsm4(bfr[jp], sBuf + bbase[jp]
                                 + (((chb + 2 * s + b_chi) ^ bswz) << 4));
#pragma unroll
                for (int i = 0; i < 2; i++)
#pragma unroll
                    for (int j = 0; j < 4; j++)
                        mma16816(acc[i][j], afr[i], &bfr[j >> 1][(j & 1) * 2]);
            }
        }

        // epilogue on register fragments
        {
            const float* Ct = Cs + t * 128 + warp_c * 32 + 2 * (lane & 3);
            float cc[8];
#pragma unroll
            for (int j = 0; j < 4; j++) { cc[2*j] = Ct[j*8]; cc[2*j+1] = Ct[j*8+1]; }
#pragma unroll
            for (int i = 0; i < 2; i++)
#pragma unroll
                for (int h = 0; h < 2; h++) {
                    float p[8];
#pragma unroll
                    for (int j = 0; j < 4; j++) {
                        p[2*j]   = fmaf(2.f, acc[i][j][2*h],     cc[2*j]);
                        p[2*j+1] = fmaf(2.f, acc[i][j][2*h + 1], cc[2*j+1]);
                    }
                    float tm = p[0];
#pragma unroll
                    for (int j = 1; j < 8; j++) tm = fmaxf(tm, p[j]);
                    const int r4 = i * 2 + h;
                    if (tm > rmax[r4] - 0.0090f) {  // else all exps underflow to 0
                        float nm = fmaxf(tm, rmax[r4]);
                        float s2 = 0.f;
#pragma unroll
                        for (int j = 0; j < 8; j++)
                            s2 += __expf((p[j] - nm) * IEPS);
                        rsum[r4] = rsum[r4] * __expf((rmax[r4] - nm) * IEPS) + s2;
                        rmax[r4] = nm;
                    }
                }
#pragma unroll
            for (int i = 0; i < 2; i++)
#pragma unroll
                for (int j = 0; j < 4; j++)
#pragma unroll
                    for (int q = 0; q < 4; q++) acc[i][j][q] = 0.f;
        }
    }

    // in-warp combine over the 4 lanes sharing a row
#pragma unroll
    for (int r4 = 0; r4 < 4; r4++) {
        float m = rmax[r4], s = rsum[r4];
#pragma unroll
        for (int off = 1; off <= 2; off <<= 1) {
            float om = __shfl_xor_sync(0xffffffffu, m, off);
            float os = __shfl_xor_sync(0xffffffffu, s, off);
            float nm = fmaxf(m, om);
            s = s * __expf((m - nm) * IEPS) + os * __expf((om - nm) * IEPS);
            m = nm;
        }
        if ((lane & 3) == 0) {
            int rl = warp_r * 32 + (r4 >> 1) * 16 + (r4 & 1) * 8 + (lane >> 2);
            comb[(rl * 4 + warp_c) * 2]     = m;
            comb[(rl * 4 + warp_c) * 2 + 1] = s;
        }
    }
    __syncthreads();

    double contrib = 0.0;
    if (tid < 64) {
        float M = comb[tid * 8], S = comb[tid * 8 + 1];
#pragma unroll
        for (int w = 1; w < 4; w++) {
            float m = comb[(tid * 4 + w) * 2], s = comb[(tid * 4 + w) * 2 + 1];
            float nm = fmaxf(M, m);
            S = S * __expf((M - nm) * IEPS) + s * __expf((m - nm) * IEPS);
            M = nm;
        }
        int row = r0 + tid;
        float val = sqCur[curBase + row] - M - EPSF * logf(S);
        out[64 + (dir ? BTN : 0) + curBase + row] = val;
        contrib = (double)__expf(loga[curBase + row]) * (double)val;
    }
    dsm[tid] = contrib;
    __syncthreads();
    for (int s = 128; s > 0; s >>= 1) {
        if (tid < s) dsm[tid] += dsm[tid + s];
        __syncthreads();
    }
    if (tid == 0) g_lossPart[step & 1][bid] = dsm[0];

    // finish the PREVIOUS step's loss (written by the previous launch)
    if (bid == 0 && step > 1 && tid < 32) {
        double s = 0.0;
#pragma unroll
        for (int j = 0; j < 8; j++) s += g_lossPart[(step - 1) & 1][tid * 8 + j];
#pragma unroll
        for (int off = 16; off > 0; off >>= 1)
            s += __shfl_xor_sync(0xffffffffu, s, off);
        if (tid == 0) {
            float L = (float)s;
#pragma unroll
            for (int bq = 0; bq < BB; bq++) out[bq * TT + step - 1] = L;
        }
    }
}

// final step's loss
__global__ void loss_finish(float* __restrict__ out) {
    __shared__ double sm[128];
    int tid = threadIdx.x;
    sm[tid] = g_lossPart[(TT - 1) & 1][tid] + g_lossPart[(TT - 1) & 1][tid + 128];
    __syncthreads();
    for (int s = 64; s > 0; s >>= 1) {
        if (tid < s) sm[tid] += sm[tid + s];
        __syncthreads();
    }
    if (tid < 4) out[tid * TT + (TT - 1)] = (float)sm[0];
}

extern "C" void kernel_launch(void* const* d_in, const int* in_sizes, int n_in,
                              void* d_out, int out_size) {
    const float* x    = (const float*)d_in[0];
    const float* y    = (const float*)d_in[1];
    const float* loga = (const float*)d_in[2];
    const float* logb = (const float*)d_in[3];
    float* out = (float*)d_out;

    cudaFuncSetAttribute(main_kernel, cudaFuncAttributeMaxDynamicSharedMemorySize,
                         SMEM_TOT);

    split_kernel<<<16384, 256>>>(x, y);
    norms_kernel<<<1024, 256>>>(x, y);
    init_kernel<<<32, 256>>>(out);
    for (int step = 1; step < TT; step++) {
        main_kernel<<<256, 256, SMEM_TOT>>>(step, loga, logb, out);
    }
    loss_finish<<<1, 128>>>(out);
}

// round 11
// speedup vs baseline: 3.6209x; 1.0634x over previous
#include <cuda_runtime.h>
#include <cuda_bf16.h>
#include <math.h>
#include <stdint.h>

#define BB   4
#define TT   16
#define NN   2048
#define DD   64
#define EPSF 1e-4f
#define IEPS 1e4f
#define BTN  (BB*TT*NN)   // 131072 = 2^17

typedef unsigned long long u64;

// static device scratch (no allocations)
__device__ float  g_sqx[BTN];
__device__ float  g_sqy[BTN];
__device__ double g_lossPart[2][256];
// bf16 split storage: per row 128 bf16: [0:64]=hi, [64:128]=lo
__device__ __nv_bfloat16 g_xs[(size_t)BTN * 128];
__device__ __nv_bfloat16 g_ys[(size_t)BTN * 128];

__device__ __forceinline__ uint32_t smem_u32(const void* p) {
    uint32_t a;
    asm("{ .reg .u64 t; cvta.to.shared.u64 t, %1; cvt.u32.u64 %0, t; }"
        : "=r"(a) : "l"(p));
    return a;
}
__device__ __forceinline__ void ldsm4(uint32_t* r, uint32_t addr) {
    asm volatile("ldmatrix.sync.aligned.m8n8.x4.shared.b16 {%0,%1,%2,%3}, [%4];"
        : "=r"(r[0]), "=r"(r[1]), "=r"(r[2]), "=r"(r[3]) : "r"(addr));
}
__device__ __forceinline__ void mma16816(float* d, const uint32_t* a,
                                         const uint32_t* b) {
    asm volatile(
        "mma.sync.aligned.m16n8k16.row.col.f32.bf16.bf16.f32 "
        "{%0,%1,%2,%3}, {%4,%5,%6,%7}, {%8,%9}, {%0,%1,%2,%3};"
        : "+f"(d[0]), "+f"(d[1]), "+f"(d[2]), "+f"(d[3])
        : "r"(a[0]), "r"(a[1]), "r"(a[2]), "r"(a[3]), "r"(b[0]), "r"(b[1]));
}
__device__ __forceinline__ void cpasync16(uint32_t sm, const void* g) {
    asm volatile("cp.async.cg.shared.global [%0], [%1], 16;"
                 :: "r"(sm), "l"(g));
}
#define CP_COMMIT() asm volatile("cp.async.commit_group;" ::: "memory")

// ---------------- small kernels ----------------
__global__ void split_kernel(const float* __restrict__ x, const float* __restrict__ y) {
    int id = blockIdx.x * 256 + threadIdx.x;       // 0 .. 2*BTN*16-1
    int kind = id >> 21;                            // BTN*16 = 2^21
    int r = id & ((1 << 21) - 1);
    int row = r >> 4, c4 = (r & 15) << 2;
    const float* src = (kind ? y : x) + (size_t)row * DD + c4;
    float4 v = *(const float4*)src;
    union { __nv_bfloat16 h[4]; u64 v; } H, L;
    H.h[0] = __float2bfloat16(v.x); L.h[0] = __float2bfloat16(v.x - __bfloat162float(H.h[0]));
    H.h[1] = __float2bfloat16(v.y); L.h[1] = __float2bfloat16(v.y - __bfloat162float(H.h[1]));
    H.h[2] = __float2bfloat16(v.z); L.h[2] = __float2bfloat16(v.z - __bfloat162float(H.h[2]));
    H.h[3] = __float2bfloat16(v.w); L.h[3] = __float2bfloat16(v.w - __bfloat162float(H.h[3]));
    __nv_bfloat16* dst = (kind ? g_ys : g_xs) + (size_t)row * 128 + c4;
    *(u64*)dst = H.v;
    *(u64*)(dst + 64) = L.v;
}

__global__ void norms_kernel(const float* __restrict__ x, const float* __restrict__ y) {
    int id = blockIdx.x * 256 + threadIdx.x;
    int kind = id >> 17;
    int r = id & (BTN - 1);
    const float4* v = (const float4*)((kind ? y : x) + (size_t)r * DD);
    float s = 0.f;
#pragma unroll
    for (int k = 0; k < 16; k++) {
        float4 q = v[k];
        s += q.x * q.x + q.y * q.y + q.z * q.z + q.w * q.w;
    }
    (kind ? g_sqy : g_sqx)[r] = s;
}

__global__ void init_kernel(float* __restrict__ out) {
    int id = blockIdx.x * blockDim.x + threadIdx.x;   // 0..8191
    if (id < 4) out[id * TT] = 0.f;
    int b = id >> 11, i = id & 2047;
    out[64 + (b * TT) * NN + i] = 0.f;
    out[64 + BTN + (b * TT) * NN + i] = 0.f;
}

// ---------------- main mma.sync kernel ----------------
// grid = 256: dir(2) x b(4) x rowblock(32). Block tile 64 rows x 2048 cols.
// 2 CTAs/SM. Warp tile 16x64; A fragments resident in registers.
// SMEM: B ring stage0 0..32K | stage1 32K..64K | stage2 64K..96K (A staged
// here first) | Cs 96K..104K | comb 104K..105K | dsm 105K..107K
#define OFF_CS   98304
#define OFF_COMB 106496
#define OFF_DSM  107520
#define SMEM_TOT 109568

__global__ __launch_bounds__(256, 2)
void main_kernel(int step, const float* __restrict__ loga,
                 const float* __restrict__ logb, float* __restrict__ out) {
    extern __shared__ char smem[];
    const uint32_t sb = smem_u32(smem);
    float*  Cs   = (float*)(smem + OFF_CS);
    float*  comb = (float*)(smem + OFF_COMB);
    double* dsm  = (double*)(smem + OFF_DSM);

    const int tid = threadIdx.x;
    const int bid = blockIdx.x;
    const int dir = bid >> 7;
    const int b   = (bid >> 5) & 3;
    const int rb  = bid & 31;
    const int r0  = rb * 64;
    const int lane = tid & 31, wid = tid >> 5;
    const int warp_r = wid >> 1, warp_c = wid & 1;   // 4 x 2 warps, tile 16x64

    const size_t curBase  = (size_t)(b * TT + step) * NN;
    const size_t prevBase = curBase - NN;

    const __nv_bfloat16* Abase = (dir == 0 ? g_xs : g_ys) + (curBase + r0) * 128;
    const __nv_bfloat16* Bbase = (dir == 0 ? g_ys : g_xs) + prevBase * 128;
    const float* prevPot = out + 64 + (dir == 0 ? BTN : 0);
    const float* lvec    = (dir == 0 ? logb : loga);
    const float* sqPrev  = (dir == 0 ? g_sqy : g_sqx);
    const float* sqCur   = (dir == 0 ? g_sqx : g_sqy);

    const int ld_row0 = tid >> 4, ld_ch = tid & 15;

    // group 0: A tile (into ring stage 2) + B tile 0 (stage 0)
#pragma unroll
    for (int j = 0; j < 4; j++) {
        int row = ld_row0 + 16 * j;
        cpasync16(sb + 65536 + (uint32_t)(row * 256 + ((ld_ch ^ (row & 7)) << 4)),
                  Abase + (size_t)row * 128 + ld_ch * 8);
    }
#pragma unroll
    for (int j = 0; j < 8; j++) {
        int row = ld_row0 + 16 * j;
        cpasync16(sb + (uint32_t)(row * 256 + ((ld_ch ^ (row & 7)) << 4)),
                  Bbase + (size_t)row * 128 + ld_ch * 8);
    }
    CP_COMMIT();
    // group 1: B tile 1 (stage 1)
#pragma unroll
    for (int j = 0; j < 8; j++) {
        int row = ld_row0 + 16 * j;
        cpasync16(sb + 32768 + (uint32_t)(row * 256 + ((ld_ch ^ (row & 7)) << 4)),
                  Bbase + (size_t)(128 + row) * 128 + ld_ch * 8);
    }
    CP_COMMIT();
    // c vector
#pragma unroll
    for (int j = 0; j < 8; j++) {
        int col = tid + 256 * j;
        Cs[col] = prevPot[prevBase + col] + EPSF * lvec[prevBase + col]
                - sqPrev[prevBase + col];
    }

    // wait A (+B0), extract A fragments once for the whole kernel
    asm volatile("cp.async.wait_group 1;" ::: "memory");
    __syncthreads();

    uint32_t afr[2][4][4];   // [hilo][kstep][4] — 32 regs, resident
    {
        const int arow = warp_r * 16 + (lane & 15);
        const uint32_t ab = sb + 65536 + (uint32_t)(arow * 256);
        const int aswz = arow & 7, achi = lane >> 4;
#pragma unroll
        for (int hl = 0; hl < 2; hl++)
#pragma unroll
            for (int s = 0; s < 4; s++)
                ldsm4(afr[hl][s], ab + (((hl * 8 + 2 * s + achi) ^ aswz) << 4));
    }
    __syncthreads();   // all warps done reading A from stage 2

    const int b_row = (lane & 7) + ((lane >> 4) & 1) * 8;
    const int b_chi = (lane >> 3) & 1;
    const int bswz  = lane & 7;
    uint32_t bbase[4];
#pragma unroll
    for (int jp = 0; jp < 4; jp++)
        bbase[jp] = (uint32_t)((warp_c * 64 + jp * 16 + b_row) * 256);

    float acc[8][4];
#pragma unroll
    for (int j = 0; j < 8; j++)
#pragma unroll
        for (int q = 0; q < 4; q++) acc[j][q] = 0.f;

    float rmax[2], rsum[2];
    rmax[0] = rmax[1] = -INFINITY; rsum[0] = rsum[1] = 0.f;

#pragma unroll 1
    for (int t = 0; t < 16; t++) {
        if (t < 15) asm volatile("cp.async.wait_group 1;" ::: "memory");
        else        asm volatile("cp.async.wait_group 0;" ::: "memory");
        __syncthreads();   // tile t visible; stage (t+2)%3 free

        if (t + 2 < 16) {
            const __nv_bfloat16* Bt = Bbase + (size_t)(t + 2) * 128 * 128;
            uint32_t Bd = sb + (uint32_t)(((t + 2) % 3) * 32768);
#pragma unroll
            for (int j = 0; j < 8; j++) {
                int row = ld_row0 + 16 * j;
                cpasync16(Bd + (uint32_t)(row * 256 + ((ld_ch ^ (row & 7)) << 4)),
                          Bt + (size_t)row * 128 + ld_ch * 8);
            }
            CP_COMMIT();
        }

        const uint32_t sBuf = sb + (uint32_t)((t % 3) * 32768);

        // mainloop: per k-step load B-hi/B-lo frags, 24 MMAs
#pragma unroll
        for (int s = 0; s < 4; s++) {
            uint32_t bhi[4][4], blo[4][4];
#pragma unroll
            for (int jp = 0; jp < 4; jp++)
                ldsm4(bhi[jp], sBuf + bbase[jp] + (((2 * s + b_chi) ^ bswz) << 4));
#pragma unroll
            for (int j = 0; j < 8; j++)
                mma16816(acc[j], afr[0][s], &bhi[j >> 1][(j & 1) * 2]);
#pragma unroll
            for (int j = 0; j < 8; j++)
                mma16816(acc[j], afr[1][s], &bhi[j >> 1][(j & 1) * 2]);
#pragma unroll
            for (int jp = 0; jp < 4; jp++)
                ldsm4(blo[jp], sBuf + bbase[jp] + (((8 + 2 * s + b_chi) ^ bswz) << 4));
#pragma unroll
            for (int j = 0; j < 8; j++)
                mma16816(acc[j], afr[0][s], &blo[j >> 1][(j & 1) * 2]);
        }

        // epilogue: p = 2*dot + c; streaming softmin with underflow skip
        {
            const float* Ct = Cs + t * 128 + warp_c * 64 + 2 * (lane & 3);
            float cc[16];
#pragma unroll
            for (int j = 0; j < 8; j++) {
                cc[2*j]   = Ct[j * 8];
                cc[2*j+1] = Ct[j * 8 + 1];
            }
#pragma unroll
            for (int h = 0; h < 2; h++) {
                float p[16];
#pragma unroll
                for (int j = 0; j < 8; j++) {
                    p[2*j]   = fmaf(2.f, acc[j][2*h],     cc[2*j]);
                    p[2*j+1] = fmaf(2.f, acc[j][2*h + 1], cc[2*j+1]);
                }
                float tm = p[0];
#pragma unroll
                for (int j = 1; j < 16; j++) tm = fmaxf(tm, p[j]);
                if (tm > rmax[h] - 0.0090f) {   // else all exps underflow to 0
                    float nm = fmaxf(tm, rmax[h]);
                    float s2 = 0.f;
#pragma unroll
                    for (int j = 0; j < 16; j++)
                        s2 += __expf((p[j] - nm) * IEPS);
                    rsum[h] = rsum[h] * __expf((rmax[h] - nm) * IEPS) + s2;
                    rmax[h] = nm;
                }
            }
#pragma unroll
            for (int j = 0; j < 8; j++)
#pragma unroll
                for (int q = 0; q < 4; q++) acc[j][q] = 0.f;
        }
    }

    // in-warp combine over the 4 lanes sharing a row
#pragma unroll
    for (int h = 0; h < 2; h++) {
        float m = rmax[h], s = rsum[h];
#pragma unroll
        for (int off = 1; off <= 2; off <<= 1) {
            float om = __shfl_xor_sync(0xffffffffu, m, off);
            float os = __shfl_xor_sync(0xffffffffu, s, off);
            float nm = fmaxf(m, om);
            s = s * __expf((m - nm) * IEPS) + os * __expf((om - nm) * IEPS);
            m = nm;
        }
        if ((lane & 3) == 0) {
            int rl = warp_r * 16 + h * 8 + (lane >> 2);
            comb[(rl * 2 + warp_c) * 2]     = m;
            comb[(rl * 2 + warp_c) * 2 + 1] = s;
        }
    }
    __syncthreads();

    double contrib = 0.0;
    if (tid < 64) {
        float m0 = comb[tid * 4],     s0 = comb[tid * 4 + 1];
        float m1 = comb[tid * 4 + 2], s1 = comb[tid * 4 + 3];
        float M = fmaxf(m0, m1);
        float S = s0 * __expf((m0 - M) * IEPS) + s1 * __expf((m1 - M) * IEPS);
        int row = r0 + tid;
        float val = sqCur[curBase + row] - M - EPSF * logf(S);
        out[64 + (dir ? BTN : 0) + curBase + row] = val;
        contrib = (double)__expf(loga[curBase + row]) * (double)val;
    }
    dsm[tid] = contrib;
    __syncthreads();
    for (int s = 128; s > 0; s >>= 1) {
        if (tid < s) dsm[tid] += dsm[tid + s];
        __syncthreads();
    }
    if (tid == 0) g_lossPart[step & 1][bid] = dsm[0];

    // finish the PREVIOUS step's loss (written by the previous launch)
    if (bid == 0 && step > 1 && tid < 32) {
        double s = 0.0;
#pragma unroll
        for (int j = 0; j < 8; j++) s += g_lossPart[(step - 1) & 1][tid * 8 + j];
#pragma unroll
        for (int off = 16; off > 0; off >>= 1)
            s += __shfl_xor_sync(0xffffffffu, s, off);
        if (tid == 0) {
            float L = (float)s;
#pragma unroll
            for (int bq = 0; bq < BB; bq++) out[bq * TT + step - 1] = L;
        }
    }
}

// final step's loss
__global__ void loss_finish(float* __restrict__ out) {
    __shared__ double sm[128];
    int tid = threadIdx.x;
    sm[tid] = g_lossPart[(TT - 1) & 1][tid] + g_lossPart[(TT - 1) & 1][tid + 128];
    __syncthreads();
    for (int s = 64; s > 0; s >>= 1) {
        if (tid < s) sm[tid] += sm[tid + s];
        __syncthreads();
    }
    if (tid < 4) out[tid * TT + (TT - 1)] = (float)sm[0];
}

extern "C" void kernel_launch(void* const* d_in, const int* in_sizes, int n_in,
                              void* d_out, int out_size) {
    const float* x    = (const float*)d_in[0];
    const float* y    = (const float*)d_in[1];
    const float* loga = (const float*)d_in[2];
    const float* logb = (const float*)d_in[3];
    float* out = (float*)d_out;

    cudaFuncSetAttribute(main_kernel, cudaFuncAttributeMaxDynamicSharedMemorySize,
                         SMEM_TOT);

    split_kernel<<<16384, 256>>>(x, y);
    norms_kernel<<<1024, 256>>>(x, y);
    init_kernel<<<32, 256>>>(out);
    for (int step = 1; step < TT; step++) {
        main_kernel<<<256, 256, SMEM_TOT>>>(step, loga, logb, out);
    }
    loss_finish<<<1, 128>>>(out);
}